// round 7
// baseline (speedup 1.0000x reference)
#include <cuda_runtime.h>

#define ITEMS 32
#define BLOCK 224
#define CHUNK (ITEMS * BLOCK)   // 7168 samples/block -> G=586, one wave @4 CTA/SM (896 thr)
#define NWARP (BLOCK / 32)      // 7
#define MAXBLKS 4096

__device__ float2 g_agg[MAXBLKS];            // per-block zero-state end state
__device__ float2 g_thr[MAXBLKS * BLOCK];    // per-thread block-local inclusive end state

// Affine map s' = M s + v, M lower-triangular [[m00,0],[m10,m11]]
struct Aff { float m00, m10, m11, v0, v1; };

__device__ __forceinline__ Aff aff_combine(const Aff& B, const Aff& A) {
    Aff r;
    r.m00 = B.m00 * A.m00;
    r.m10 = fmaf(B.m10, A.m00, B.m11 * A.m10);
    r.m11 = B.m11 * A.m11;
    r.v0  = fmaf(B.m00, A.v0, B.v0);
    r.v1  = fmaf(B.m10, A.v0, fmaf(B.m11, A.v1, B.v1));
    return r;
}

__device__ __forceinline__ float2 aff_apply(const Aff& A, float2 s) {
    float2 r;
    r.x = fmaf(A.m00, s.x, A.v0);
    r.y = fmaf(A.m10, s.x, fmaf(A.m11, s.y, A.v1));
    return r;
}

__device__ __forceinline__ Aff aff_shfl_up(const Aff& a, int d) {
    Aff r;
    r.m00 = __shfl_up_sync(0xffffffffu, a.m00, d);
    r.m10 = __shfl_up_sync(0xffffffffu, a.m10, d);
    r.m11 = __shfl_up_sync(0xffffffffu, a.m11, d);
    r.v0  = __shfl_up_sync(0xffffffffu, a.v0,  d);
    r.v1  = __shfl_up_sync(0xffffffffu, a.v1,  d);
    return r;
}

__device__ __forceinline__ void get_params(const float* __restrict__ p,
                                           float& c1, float& c2,
                                           float& attack, float& decay, float& gain) {
    attack = fmaxf(p[0], 1e-7f);
    decay  = fmaxf(p[1], 1e-7f);
    c1 = fminf(fmaxf(p[2], 1e-7f), 0.99f);   // lowpass
    c2 = fminf(fmaxf(p[3], 1e-7f), 0.99f);   // highpass
    gain = fmaxf(p[4], 1e-7f);
}

__device__ __forceinline__ void mat_mul(float& c00, float& c10, float& c11,
                                        float a00, float a10, float a11,
                                        float b00, float b10, float b11) {
    c00 = a00 * b00;
    c10 = fmaf(a10, b00, a11 * b10);
    c11 = a11 * b11;
}

__device__ __forceinline__ void mat_sq_k(float& m00, float& m10, float& m11, int k) {
    #pragma unroll 1
    for (int i = 0; i < k; i++) {
        float n00 = m00 * m00;
        float n10 = m10 * (m00 + m11);
        float n11 = m11 * m11;
        m00 = n00; m10 = n10; m11 = n11;
    }
}

// ---------------------------------------------------------------------------
// Pass 1: stride-4 zero-state sweep; block scan; publish per-thread inclusive
// states + block aggregate.
// ---------------------------------------------------------------------------
__global__ void __launch_bounds__(BLOCK, 4)
ng_pass1(const float* __restrict__ params, const float* __restrict__ x, int n) {
    float c1, c2, at, de, g;
    get_params(params, c1, c2, at, de, g);
    const float b1 = 1.0f - c1;
    const float d  = c2 * (c1 - 1.0f);
    const float bb = c2 * b1;

    const int tid = threadIdx.x;
    const int bid = blockIdx.x;
    const long base = (long)bid * CHUNK + (long)tid * ITEMS;

    float xv[ITEMS];
    if (base + ITEMS <= n) {
        const float4* xp = (const float4*)(x + base);
        #pragma unroll
        for (int k = 0; k < ITEMS / 4; k++) {
            float4 v = xp[k];
            xv[4*k+0] = v.x; xv[4*k+1] = v.y; xv[4*k+2] = v.z; xv[4*k+3] = v.w;
        }
    } else {
        #pragma unroll
        for (int j = 0; j < ITEMS; j++)
            xv[j] = (base + j < n) ? x[base + j] : 0.0f;
    }

    // stride-4 constants
    const float A2_00 = c1 * c1, A2_10 = d * (c1 + c2), A2_11 = c2 * c2;
    const float A4_00 = A2_00 * A2_00, A4_10 = A2_10 * (A2_00 + A2_11), A4_11 = A2_11 * A2_11;
    const float q0x = b1,          q0y = bb;                                // b
    const float q1x = c1 * q0x,    q1y = fmaf(d, q0x, c2 * q0y);            // A b
    const float q2x = c1 * q1x,    q2y = fmaf(d, q1x, c2 * q1y);            // A^2 b
    const float q3x = c1 * q2x,    q3y = fmaf(d, q2x, c2 * q2y);            // A^3 b

    float y1 = 0.0f, y2 = 0.0f;
    #pragma unroll
    for (int k = 0; k < ITEMS / 4; k++) {
        float xa = xv[4*k+0], xb = xv[4*k+1], xc = xv[4*k+2], xd = xv[4*k+3];
        float u0 = fmaf(q2x, xb, q3x * xa) + fmaf(q0x, xd, q1x * xc);
        float u1 = fmaf(q2y, xb, q3y * xa) + fmaf(q0y, xd, q1y * xc);
        float y1n = fmaf(A4_00, y1, u0);
        y2 = fmaf(A4_10, y1, fmaf(A4_11, y2, u1));
        y1 = y1n;
    }

    // segment matrix A^32 (5 squarings)
    float m00 = c1, m10 = d, m11 = c2;
    mat_sq_k(m00, m10, m11, 5);
    Aff a = {m00, m10, m11, y1, y2};

    const int lane = tid & 31, wid = tid >> 5;
    #pragma unroll
    for (int dd = 1; dd < 32; dd <<= 1) {
        Aff o = aff_shfl_up(a, dd);
        if (lane >= dd) a = aff_combine(a, o);
    }

    __shared__ Aff    wtot[NWARP];
    __shared__ float2 win[NWARP];
    if (lane == 31) wtot[wid] = a;
    __syncthreads();
    if (tid == 0) {
        float2 s = make_float2(0.0f, 0.0f);
        #pragma unroll
        for (int w = 0; w < NWARP; w++) { win[w] = s; s = aff_apply(wtot[w], s); }
        g_agg[bid] = s;
    }
    __syncthreads();

    float2 incl = aff_apply(a, win[wid]);
    g_thr[bid * BLOCK + tid] = incl;
}

// ---------------------------------------------------------------------------
// Pass 2: closed-form seeding + parallel lookback + stride-2 replay + envelope.
// ---------------------------------------------------------------------------
__global__ void __launch_bounds__(BLOCK, 4)
ng_pass3(const float* __restrict__ params, const float* __restrict__ x,
         float* __restrict__ out, int n) {
    float c1, c2, at, de, g;
    get_params(params, c1, c2, at, de, g);
    const float b1 = 1.0f - c1;
    const float d  = c2 * (c1 - 1.0f);
    const float bb = c2 * b1;

    const int tid  = threadIdx.x;
    const int bid  = blockIdx.x;
    const int lane = tid & 31, wid = tid >> 5;
    const long base = (long)bid * CHUNK + (long)tid * ITEMS;
    const bool full = (base + ITEMS) <= n;

    // ---- issue sample loads early (overlap with powering + lookback) ----
    float xv[ITEMS];
    if (full) {
        const float4* xp = (const float4*)(x + base);
        #pragma unroll
        for (int k = 0; k < ITEMS / 4; k++) {
            float4 v = xp[k];
            xv[4*k+0] = v.x; xv[4*k+1] = v.y; xv[4*k+2] = v.z; xv[4*k+3] = v.w;
        }
    } else {
        #pragma unroll
        for (int j = 0; j < ITEMS; j++)
            xv[j] = (base + j < n) ? x[base + j] : 0.0f;
    }

    // ---- previous thread's block-local inclusive state ----
    float2 vp = make_float2(0.0f, 0.0f);
    if (tid > 0) vp = __ldg(&g_thr[bid * BLOCK + tid - 1]);

    // ---- powering chains (A32 = A^ITEMS) ----
    float p00 = c1, p10 = d, p11 = c2;
    mat_sq_k(p00, p10, p11, 5);                   // A^32

    // Mseed = A32^tid ; capture A32^{32,64,128} to form A_C = A32^224 = A^CHUNK
    float Ms00 = 1.0f, Ms10 = 0.0f, Ms11 = 1.0f;
    float C500 = 1.0f, C510 = 0.0f, C511 = 1.0f;
    float C600 = 1.0f, C610 = 0.0f, C611 = 1.0f;
    float C700 = 1.0f, C710 = 0.0f, C711 = 1.0f;
    #pragma unroll
    for (int b = 0; b < 8; b++) {
        if (b == 5) { C500 = p00; C510 = p10; C511 = p11; }
        if (b == 6) { C600 = p00; C610 = p10; C611 = p11; }
        if (b == 7) { C700 = p00; C710 = p10; C711 = p11; }
        if ((tid >> b) & 1) {
            float t00, t10, t11;
            mat_mul(t00, t10, t11, Ms00, Ms10, Ms11, p00, p10, p11);
            Ms00 = t00; Ms10 = t10; Ms11 = t11;
        }
        float q00, q10, q11;
        mat_mul(q00, q10, q11, p00, p10, p11, p00, p10, p11);
        p00 = q00; p10 = q10; p11 = q11;
    }
    // A_C = A32^224 = A32^32 * A32^64 * A32^128
    float AC00, AC10, AC11, T00, T10, T11;
    mat_mul(T00, T10, T11, C500, C510, C511, C600, C610, C611);
    mat_mul(AC00, AC10, AC11, T00, T10, T11, C700, C710, C711);

    // Ml = A_C^tid ; capture A_C^{32,64,128} to form S = A_C^224 = A_C^BLOCK
    float Ml00 = 1.0f, Ml10 = 0.0f, Ml11 = 1.0f;
    p00 = AC00; p10 = AC10; p11 = AC11;
    float D500 = 1.0f, D510 = 0.0f, D511 = 1.0f;
    float D600 = 1.0f, D610 = 0.0f, D611 = 1.0f;
    float D700 = 1.0f, D710 = 0.0f, D711 = 1.0f;
    #pragma unroll
    for (int b = 0; b < 8; b++) {
        if (b == 5) { D500 = p00; D510 = p10; D511 = p11; }
        if (b == 6) { D600 = p00; D610 = p10; D611 = p11; }
        if (b == 7) { D700 = p00; D710 = p10; D711 = p11; }
        if ((tid >> b) & 1) {
            float t00, t10, t11;
            mat_mul(t00, t10, t11, Ml00, Ml10, Ml11, p00, p10, p11);
            Ml00 = t00; Ml10 = t10; Ml11 = t11;
        }
        float q00, q10, q11;
        mat_mul(q00, q10, q11, p00, p10, p11, p00, p10, p11);
        p00 = q00; p10 = q10; p11 = q11;
    }
    float S00, S10, S11;
    mat_mul(T00, T10, T11, D500, D510, D511, D600, D610, D611);
    mat_mul(S00, S10, S11, T00, T10, T11, D700, D710, D711);

    // ---- parallel lookback: s_in = sum_{dd=0}^{bid-1} A_C^dd * agg[bid-1-dd] ----
    float r0 = 0.0f, r1 = 0.0f;
    for (int dd = tid; dd < bid; dd += BLOCK) {
        float2 v = __ldg(&g_agg[bid - 1 - dd]);
        r0 = fmaf(Ml00, v.x, r0);
        r1 = fmaf(Ml10, v.x, fmaf(Ml11, v.y, r1));
        float t00, t10, t11;
        mat_mul(t00, t10, t11, Ml00, Ml10, Ml11, S00, S10, S11);
        Ml00 = t00; Ml10 = t10; Ml11 = t11;
    }
    #pragma unroll
    for (int dd = 16; dd > 0; dd >>= 1) {
        r0 += __shfl_xor_sync(0xffffffffu, r0, dd);
        r1 += __shfl_xor_sync(0xffffffffu, r1, dd);
    }
    __shared__ float2 wred[NWARP];
    if (lane == 0) wred[wid] = make_float2(r0, r1);
    __syncthreads();
    float sinx = 0.0f, siny = 0.0f;
    #pragma unroll
    for (int w = 0; w < NWARP; w++) { sinx += wred[w].x; siny += wred[w].y; }

    // ---- closed-form thread seed ----
    float y1 = fmaf(Ms00, sinx, vp.x);
    float y2 = fmaf(Ms10, sinx, fmaf(Ms11, siny, vp.y));

    // ---- envelope (geometric); pair-stride chains ----
    const float inv_n1 = 1.0f / (float)(n - 1);
    const float k1 = 1.0f / de;
    const float k2 = 1.0f / at + k1;
    const float t0 = (float)base * inv_n1;
    float e1 = g * __expf(-t0 * k1);
    float e2 = g * __expf(-t0 * k2);
    const float r1c = __expf(-inv_n1 * k1);
    const float r2c = __expf(-inv_n1 * k2);
    const float r1s = r1c * r1c;
    const float r2s = r2c * r2c;

    // ---- stride-2 replay constants ----
    const float A2_00 = c1 * c1, A2_10 = d * (c1 + c2), A2_11 = c2 * c2;
    const float Ab0 = c1 * b1;
    const float Ab1 = fmaf(d, b1, c2 * bb);

    if (full) {
        float4* op = (float4*)(out + base);
        #pragma unroll
        for (int k = 0; k < ITEMS / 4; k++) {
            float o[4];
            #pragma unroll
            for (int pr = 0; pr < 2; pr++) {
                float xa = xv[4*k + 2*pr], xb = xv[4*k + 2*pr + 1];
                // mid state (after xa) — off the critical chain
                float y2m = fmaf(d, y1, fmaf(c2, y2, bb * xa));
                // pair update (after xa, xb)
                float u0 = fmaf(Ab0, xa, b1 * xb);
                float u1 = fmaf(Ab1, xa, bb * xb);
                float y1n = fmaf(A2_00, y1, u0);
                y2 = fmaf(A2_10, y1, fmaf(A2_11, y2, u1));
                y1 = y1n;
                // envelope for both samples of the pair
                float ea = e1 - e2;
                float eb = fmaf(e1, r1c, -(e2 * r2c));
                e1 *= r1s; e2 *= r2s;
                o[2*pr]     = y2m * ea;
                o[2*pr + 1] = y2  * eb;
            }
            float4 ov; ov.x = o[0]; ov.y = o[1]; ov.z = o[2]; ov.w = o[3];
            op[k] = ov;
        }
    } else {
        // tail path: stride-1, masked stores
        #pragma unroll
        for (int j = 0; j < ITEMS; j++) {
            float y1n = fmaf(c1, y1, b1 * xv[j]);
            y2 = c2 * (y2 + (y1n - y1));
            y1 = y1n;
            float v = y2 * (e1 - e2);
            e1 *= r1c; e2 *= r2c;
            if (base + j < n) out[base + j] = v;
        }
    }
}

// ---------------------------------------------------------------------------
extern "C" void kernel_launch(void* const* d_in, const int* in_sizes, int n_in,
                              void* d_out, int out_size) {
    int i_par = 0, i_noise = 1;
    if (n_in >= 2 && in_sizes[0] > in_sizes[1]) { i_par = 1; i_noise = 0; }
    const float* params = (const float*)d_in[i_par];
    const float* noise  = (const float*)d_in[i_noise];
    float* out = (float*)d_out;
    const int n = in_sizes[i_noise];
    int G = (n + CHUNK - 1) / CHUNK;
    if (G > MAXBLKS) G = MAXBLKS;  // n = 2^22 -> G = 586 (single wave @ 4 CTAs/SM)

    ng_pass1<<<G, BLOCK>>>(params, noise, n);
    ng_pass3<<<G, BLOCK>>>(params, noise, out, n);
}